// round 13
// baseline (speedup 1.0000x reference)
#include <cuda_runtime.h>

// ---------------------------------------------------------------------------
// Net_VIF: 6 chained quadrilinear (4D) LUT interpolations, fully fused.
// Numerics bit-identical to R10..R12 per pixel: sequential rn weight chain,
// fold c=0..15, packed f32x2 mul/add per channel pair (deterministic
// rel_err 9.274097e-4 across R7-R12 binaries).
//
// R13 = R11 fetch/exchange/fold + ILP-2:
//  - each thread carries TWO pixels; per stage: fetchA, fetchB, xposeA,
//    foldA, xposeB, foldB -> B's 8 LDG.256 overlap A's latency, A's
//    transpose/fold ALU runs under B's memory time. Breaks the per-warp
//    burst serialization that pinned L1 at ~78% across 16/20/24 warps.
//  - __launch_bounds__(128, 3): 170-reg cap for the ~160-reg dual state.
// ---------------------------------------------------------------------------

#define D   17
#define D2  289
#define D3  4913
#define D4  83521
#define N_LUTS 6

typedef unsigned long long u64;

// block layout: entry = cell*8 + p, p = b1*4 + b2*2 + b3.
// 6 * 83521 * 8 * 16B = ~64 MB static device scratch (L2-resident).
__device__ __align__(128) float4 g_lutB[N_LUTS][D4 * 8];

__global__ void lut_pack_kernel(const float* __restrict__ s0, const float* __restrict__ s1,
                                const float* __restrict__ s2, const float* __restrict__ s3,
                                const float* __restrict__ s4, const float* __restrict__ s5) {
    int idx = blockIdx.x * blockDim.x + threadIdx.x;   // (cell, element)
    if (idx >= D4 * 8) return;
    int cell = idx >> 3;
    int p    = idx & 7;
    int which = blockIdx.y;
    const float* src = (which == 0) ? s0 : (which == 1) ? s1 : (which == 2) ? s2
                     : (which == 3) ? s3 : (which == 4) ? s4 : s5;
    bool c4 = (which != 5);
    int i3 = cell % D;
    int i2 = (cell / D) % D;
    int i1 = (cell / D2) % D;
    int b1 = p >> 2, b2 = (p >> 1) & 1, b3 = p & 1;
    float4 v = make_float4(0.0f, 0.0f, 0.0f, 0.0f);
    if ((i1 + b1) <= D - 1 && (i2 + b2) <= D - 1 && (i3 + b3) <= D - 1) {
        int o = cell + b1 * D2 + b2 * D + b3;
        v.x = src[o];
        v.y = src[D4 + o];
        v.z = src[2 * D4 + o];
        v.w = c4 ? src[3 * D4 + o] : 0.0f;
    }
    g_lutB[which][idx] = v;   // warp-coalesced 128B stores
}

// -------- packed f32x2 helpers --------------------------------------------
__device__ __forceinline__ u64 mul2(u64 a, u64 b) {
    u64 r; asm("mul.rn.f32x2 %0, %1, %2;" : "=l"(r) : "l"(a), "l"(b)); return r;
}
__device__ __forceinline__ u64 add2(u64 a, u64 b) {
    u64 r; asm("add.rn.f32x2 %0, %1, %2;" : "=l"(r) : "l"(a), "l"(b)); return r;
}
__device__ __forceinline__ u64 packdup(float w) {
    u64 r; asm("mov.b64 %0, {%1, %2};" : "=l"(r) : "f"(w), "f"(w)); return r;
}
__device__ __forceinline__ u64 pack2(float a, float b) {
    u64 r; asm("mov.b64 %0, {%1, %2};" : "=l"(r) : "f"(a), "f"(b)); return r;
}

// corner payload: xy = channels (x,y), zw = channels (z,w)
struct C2 { u64 xy, zw; };

// One butterfly step on a 2-corner BUNDLE pair (32B each). Bit movement only.
__device__ __forceinline__ void xstepB(C2 (&lo)[2], C2 (&hi)[2], bool h, int m) {
    const unsigned FULL = 0xffffffffu;
#pragma unroll
    for (int t = 0; t < 2; ++t) {
        u64 s0 = h ? lo[t].xy : hi[t].xy;
        u64 s1 = h ? lo[t].zw : hi[t].zw;
        u64 r0 = __shfl_xor_sync(FULL, s0, m);
        u64 r1 = __shfl_xor_sync(FULL, s1, m);
        lo[t].xy = h ? r0 : lo[t].xy;  hi[t].xy = h ? hi[t].xy : r0;
        lo[t].zw = h ? r1 : lo[t].zw;  hi[t].zw = h ? hi[t].zw : r1;
    }
}

// Per-pixel interpolation state for one stream.
struct Stream {
    float f2, f3, g2, g3;
    float p01[4];
    C2 v[2][4][2];                    // v[j][slot][half]
};

// Compute indices/fractions and issue this stream's 8 LDG.256 (quad-coop).
__device__ __forceinline__ void fetch_stream(Stream& S,
                                             const float4* __restrict__ lut,
                                             float4 x, int s) {
    const unsigned FULL = 0xffffffffu;
    float t0 = __saturatef(x.x) * 16.0f;
    float t1 = __saturatef(x.y) * 16.0f;
    float t2 = __saturatef(x.z) * 16.0f;
    float t3 = __saturatef(x.w) * 16.0f;
    int i0 = min((int)t0, D - 2);
    int i1 = min((int)t1, D - 2);
    int i2 = min((int)t2, D - 2);
    int i3 = min((int)t3, D - 2);
    float f0 = t0 - (float)i0;
    float f1 = t1 - (float)i1;
    S.f2 = t2 - (float)i2;
    S.f3 = t3 - (float)i3;
    float g0 = 1.0f - f0, g1 = 1.0f - f1;
    S.g2 = 1.0f - S.f2;
    S.g3 = 1.0f - S.f3;
    S.p01[0] = __fmul_rn(g0, g1);
    S.p01[1] = __fmul_rn(f0, g1);
    S.p01[2] = __fmul_rn(g0, f1);
    S.p01[3] = __fmul_rn(f0, f1);
    int mybase = ((i0 * D + i1) * D + i2) * D + i3;

#pragma unroll
    for (int r = 0; r < 4; ++r) {
        int br = __shfl_sync(FULL, mybase, r, 4);   // quad-segment broadcast
#pragma unroll
        for (int j = 0; j < 2; ++j) {
            const float* p = (const float*)(lut + (size_t)(br + j * D3) * 8 + 2 * s);
            float a0, a1, a2, a3, a4, a5, a6, a7;
            asm("ld.global.nc.v8.f32 {%0,%1,%2,%3,%4,%5,%6,%7}, [%8];"
                : "=f"(a0), "=f"(a1), "=f"(a2), "=f"(a3),
                  "=f"(a4), "=f"(a5), "=f"(a6), "=f"(a7)
                : "l"(p));
            S.v[j][r][0].xy = pack2(a0, a1);
            S.v[j][r][0].zw = pack2(a2, a3);
            S.v[j][r][1].xy = pack2(a4, a5);
            S.v[j][r][1].zw = pack2(a6, a7);
        }
    }
}

// Transpose this stream's bundles back to owners and fold (reference order).
__device__ __forceinline__ float4 finish_stream(Stream& S, int s) {
    const bool h1 = (s & 1) != 0;
    const bool h2 = (s & 2) != 0;
#pragma unroll
    for (int j = 0; j < 2; ++j) {
        xstepB(S.v[j][0], S.v[j][1], h1, 1);
        xstepB(S.v[j][2], S.v[j][3], h1, 1);
        xstepB(S.v[j][0], S.v[j][2], h2, 2);
        xstepB(S.v[j][1], S.v[j][3], h2, 2);
    }

    // Sequential fold c = 0..15 (reference order), lazy weights:
    // w = rn(rn(p01[c&3] * sel2) * sel3). Corner: j = c&1; p = 4b1+2b2+b3.
    u64 accxy = 0ull, acczw = 0ull;    // bits of (+0.0f, +0.0f)
#pragma unroll
    for (int c = 0; c < 16; ++c) {
        const int j = c & 1;
        const int p = 4 * ((c >> 1) & 1) + 2 * ((c >> 2) & 1) + ((c >> 3) & 1);
        const float s2 = (c & 4) ? S.f2 : S.g2;
        const float s3 = (c & 8) ? S.f3 : S.g3;
        const float wc = __fmul_rn(__fmul_rn(S.p01[c & 3], s2), s3);
        const u64 wp = packdup(wc);
        const C2 vv = S.v[j][p >> 1][p & 1];
        accxy = add2(accxy, mul2(vv.xy, wp));
        acczw = add2(acczw, mul2(vv.zw, wp));
    }

    float4 r;
    asm("mov.b64 {%0, %1}, %2;" : "=f"(r.x), "=f"(r.y) : "l"(accxy));
    asm("mov.b64 {%0, %1}, %2;" : "=f"(r.z), "=f"(r.w) : "l"(acczw));
    return r;
}

__global__ void __launch_bounds__(128, 3)
net_vif_kernel(const float* __restrict__ vi,
               const float* __restrict__ ir,
               float* __restrict__ out) {
    const int HW = 512 * 512;                  // 1<<18
    int pA = blockIdx.x * 256 + threadIdx.x;   // pixel stream A
    int pB = pA + 128;                         // pixel stream B
    int lane = threadIdx.x & 31;
    const int s = lane & 3;

    int hwA = pA & (HW - 1), bA = pA >> 18;
    int hwB = pB & (HW - 1), bB = pB >> 18;

    const float* vA = vi + (size_t)bA * 3 * HW + hwA;
    const float* vB = vi + (size_t)bB * 3 * HW + hwB;
    float4 xA, xB;
    xA.x = vA[0];  xA.y = vA[HW];  xA.z = vA[2 * HW];
    xA.w = ir[(size_t)bA * HW + hwA];
    xB.x = vB[0];  xB.y = vB[HW];  xB.z = vB[2 * HW];
    xB.w = ir[(size_t)bB * HW + hwB];

#pragma unroll
    for (int st = 0; st < N_LUTS; ++st) {
        const float4* lut = g_lutB[st];
        Stream SA, SB;
        fetch_stream(SA, lut, xA, s);          // A's loads in flight
        fetch_stream(SB, lut, xB, s);          // B's loads in flight
        xA = finish_stream(SA, s);             // ALU under B's latency
        xB = finish_stream(SB, s);
    }

    float* oA = out + (size_t)bA * 3 * HW + hwA;
    float* oB = out + (size_t)bB * 3 * HW + hwB;
    oA[0] = xA.x;  oA[HW] = xA.y;  oA[2 * HW] = xA.z;
    oB[0] = xB.x;  oB[HW] = xB.y;  oB[2 * HW] = xB.z;
}

extern "C" void kernel_launch(void* const* d_in, const int* in_sizes, int n_in,
                              void* d_out, int out_size) {
    const float* vi = (const float*)d_in[0];   // [8,3,512,512]
    const float* ir = (const float*)d_in[1];   // [8,1,512,512]

    dim3 pg((D4 * 8 + 255) / 256, N_LUTS);
    lut_pack_kernel<<<pg, 256>>>((const float*)d_in[2], (const float*)d_in[3],
                                 (const float*)d_in[4], (const float*)d_in[5],
                                 (const float*)d_in[6], (const float*)d_in[7]);

    const int total = 8 * 512 * 512;           // 2,097,152
    net_vif_kernel<<<total / 256, 128>>>(vi, ir, (float*)d_out);
}

// round 14
// speedup vs baseline: 1.2083x; 1.2083x over previous
#include <cuda_runtime.h>

// ---------------------------------------------------------------------------
// Net_VIF: 6 chained quadrilinear (4D) LUT interpolations, fully fused.
// Numerics bit-identical to R10..R13: sequential rn weight chain, fold
// c=0..15, packed f32x2 mul/add per channel pair (deterministic
// rel_err 9.274097e-4 across R7-R13 binaries).
//
// R14 = R11 (128B-block layout, LDG.256 quad-cooperative fetch, 4x4 bundle
// transpose, lazy weights, 128 thr x 5 CTAs = 20 warps/SM) with ONE change:
//  - LUT loads use ld.global.cg (L2-only, no L1 allocation). L1 hit rate on
//    the random 64MB gather is ~0%, so L1 allocation+fill passes are pure
//    overhead — the suspected source of the 77-79% L1-utilization cap seen
//    across R10/R11/R12/R13.
// ---------------------------------------------------------------------------

#define D   17
#define D2  289
#define D3  4913
#define D4  83521
#define N_LUTS 6

typedef unsigned long long u64;

// block layout: entry = cell*8 + p, p = b1*4 + b2*2 + b3.
// 6 * 83521 * 8 * 16B = ~64 MB static device scratch (L2-resident).
__device__ __align__(128) float4 g_lutB[N_LUTS][D4 * 8];

__global__ void lut_pack_kernel(const float* __restrict__ s0, const float* __restrict__ s1,
                                const float* __restrict__ s2, const float* __restrict__ s3,
                                const float* __restrict__ s4, const float* __restrict__ s5) {
    int idx = blockIdx.x * blockDim.x + threadIdx.x;   // (cell, element)
    if (idx >= D4 * 8) return;
    int cell = idx >> 3;
    int p    = idx & 7;
    int which = blockIdx.y;
    const float* src = (which == 0) ? s0 : (which == 1) ? s1 : (which == 2) ? s2
                     : (which == 3) ? s3 : (which == 4) ? s4 : s5;
    bool c4 = (which != 5);
    int i3 = cell % D;
    int i2 = (cell / D) % D;
    int i1 = (cell / D2) % D;
    int b1 = p >> 2, b2 = (p >> 1) & 1, b3 = p & 1;
    float4 v = make_float4(0.0f, 0.0f, 0.0f, 0.0f);
    if ((i1 + b1) <= D - 1 && (i2 + b2) <= D - 1 && (i3 + b3) <= D - 1) {
        int o = cell + b1 * D2 + b2 * D + b3;
        v.x = src[o];
        v.y = src[D4 + o];
        v.z = src[2 * D4 + o];
        v.w = c4 ? src[3 * D4 + o] : 0.0f;
    }
    g_lutB[which][idx] = v;   // warp-coalesced 128B stores
}

// -------- packed f32x2 helpers (same as R7..R13) ----------------------------
__device__ __forceinline__ u64 mul2(u64 a, u64 b) {
    u64 r; asm("mul.rn.f32x2 %0, %1, %2;" : "=l"(r) : "l"(a), "l"(b)); return r;
}
__device__ __forceinline__ u64 add2(u64 a, u64 b) {
    u64 r; asm("add.rn.f32x2 %0, %1, %2;" : "=l"(r) : "l"(a), "l"(b)); return r;
}
__device__ __forceinline__ u64 packdup(float w) {
    u64 r; asm("mov.b64 %0, {%1, %2};" : "=l"(r) : "f"(w), "f"(w)); return r;
}
__device__ __forceinline__ u64 pack2(float a, float b) {
    u64 r; asm("mov.b64 %0, {%1, %2};" : "=l"(r) : "f"(a), "f"(b)); return r;
}

// corner payload: xy = channels (x,y), zw = channels (z,w)
struct C2 { u64 xy, zw; };

// One butterfly step on a 2-corner BUNDLE pair (32B each). Bit movement only.
__device__ __forceinline__ void xstepB(C2 (&lo)[2], C2 (&hi)[2], bool h, int m) {
    const unsigned FULL = 0xffffffffu;
#pragma unroll
    for (int t = 0; t < 2; ++t) {
        u64 s0 = h ? lo[t].xy : hi[t].xy;
        u64 s1 = h ? lo[t].zw : hi[t].zw;
        u64 r0 = __shfl_xor_sync(FULL, s0, m);
        u64 r1 = __shfl_xor_sync(FULL, s1, m);
        lo[t].xy = h ? r0 : lo[t].xy;  hi[t].xy = h ? hi[t].xy : r0;
        lo[t].zw = h ? r1 : lo[t].zw;  hi[t].zw = h ? hi[t].zw : r1;
    }
}

__device__ __forceinline__ float4 coop_stage(const float4* __restrict__ lut,
                                             float4 x, int lane) {
    const unsigned FULL = 0xffffffffu;
    const int s = lane & 3;          // quad member

    // Own indices / fractions (exact ops, identical to reference).
    float t0 = __saturatef(x.x) * 16.0f;
    float t1 = __saturatef(x.y) * 16.0f;
    float t2 = __saturatef(x.z) * 16.0f;
    float t3 = __saturatef(x.w) * 16.0f;
    int i0 = min((int)t0, D - 2);
    int i1 = min((int)t1, D - 2);
    int i2 = min((int)t2, D - 2);
    int i3 = min((int)t3, D - 2);
    float f0 = t0 - (float)i0;
    float f1 = t1 - (float)i1;
    float f2 = t2 - (float)i2;
    float f3 = t3 - (float)i3;
    float g0 = 1.0f - f0, g1 = 1.0f - f1, g2 = 1.0f - f2, g3 = 1.0f - f3;
    int mybase = ((i0 * D + i1) * D + i2) * D + i3;

    // Quad-cooperative 256-bit fetch: round r serves pixel (quad + r); all 4
    // lanes read that pixel's 128B line, lane s takes corners {2s, 2s+1}.
    // ld.global.cg: L2-only, no L1 allocation (hit rate ~0% anyway).
    C2 v[2][4][2];                   // v[j][slot][half]
#pragma unroll
    for (int r = 0; r < 4; ++r) {
        int br = __shfl_sync(FULL, mybase, r, 4);   // quad-segment broadcast
#pragma unroll
        for (int j = 0; j < 2; ++j) {
            const float* p = (const float*)(lut + (size_t)(br + j * D3) * 8 + 2 * s);
            float a0, a1, a2, a3, a4, a5, a6, a7;
            asm("ld.global.cg.v8.f32 {%0,%1,%2,%3,%4,%5,%6,%7}, [%8];"
                : "=f"(a0), "=f"(a1), "=f"(a2), "=f"(a3),
                  "=f"(a4), "=f"(a5), "=f"(a6), "=f"(a7)
                : "l"(p));
            v[j][r][0].xy = pack2(a0, a1);
            v[j][r][0].zw = pack2(a2, a3);
            v[j][r][1].xy = pack2(a4, a5);
            v[j][r][1].zw = pack2(a6, a7);
        }
    }

    // 4x4 bundle transpose across quad lanes (levels 1, 2): afterwards
    // v[j][k][half] = corner p = 2k + half (p = 4*b1 + 2*b2 + b3) of OWN pixel.
    const bool h1 = (s & 1) != 0;
    const bool h2 = (s & 2) != 0;
#pragma unroll
    for (int j = 0; j < 2; ++j) {
        xstepB(v[j][0], v[j][1], h1, 1);
        xstepB(v[j][2], v[j][3], h1, 1);
        xstepB(v[j][0], v[j][2], h2, 2);
        xstepB(v[j][1], v[j][3], h2, 2);
    }

    // p01[j], j = b0 + 2*b1 (reference rn(w0*w1)).
    float p01[4];
    p01[0] = __fmul_rn(g0, g1);
    p01[1] = __fmul_rn(f0, g1);
    p01[2] = __fmul_rn(g0, f1);
    p01[3] = __fmul_rn(f0, f1);

    // Sequential fold c = 0..15 (reference order) with LAZY weights:
    // w = rn(rn(p01[c&3] * sel2) * sel3) — identical rounding chain to
    // ((w0*w1)*w2)*w3; selects are compile-time per unrolled c.
    // Corner: j = b0 = c&1; p = 4*b1 + 2*b2 + b3.
    u64 accxy = 0ull, acczw = 0ull;    // bits of (+0.0f, +0.0f)
#pragma unroll
    for (int c = 0; c < 16; ++c) {
        const int j = c & 1;
        const int p = 4 * ((c >> 1) & 1) + 2 * ((c >> 2) & 1) + ((c >> 3) & 1);
        const float s2 = (c & 4) ? f2 : g2;
        const float s3 = (c & 8) ? f3 : g3;
        const float wc = __fmul_rn(__fmul_rn(p01[c & 3], s2), s3);
        const u64 wp = packdup(wc);
        const C2 vv = v[j][p >> 1][p & 1];
        accxy = add2(accxy, mul2(vv.xy, wp));
        acczw = add2(acczw, mul2(vv.zw, wp));
    }

    float4 r;
    asm("mov.b64 {%0, %1}, %2;" : "=f"(r.x), "=f"(r.y) : "l"(accxy));
    asm("mov.b64 {%0, %1}, %2;" : "=f"(r.z), "=f"(r.w) : "l"(acczw));
    return r;
}

__global__ void __launch_bounds__(128, 5)
net_vif_kernel(const float* __restrict__ vi,
               const float* __restrict__ ir,
               float* __restrict__ out) {
    const int HW = 512 * 512;                  // 1<<18
    int p  = blockIdx.x * blockDim.x + threadIdx.x;
    int hw = p & (HW - 1);
    int b  = p >> 18;
    int lane = threadIdx.x & 31;

    const float* vb = vi + (size_t)b * 3 * HW + hw;
    float4 x;
    x.x = vb[0];
    x.y = vb[HW];
    x.z = vb[2 * HW];
    x.w = ir[(size_t)b * HW + hw];

    x = coop_stage(g_lutB[0], x, lane);   // lut8
    x = coop_stage(g_lutB[1], x, lane);   // lut00
    x = coop_stage(g_lutB[2], x, lane);   // lut01
    x = coop_stage(g_lutB[3], x, lane);   // lut02
    x = coop_stage(g_lutB[4], x, lane);   // lut03
    x = coop_stage(g_lutB[5], x, lane);   // lutpgf (no final clip)

    float* ob = out + (size_t)b * 3 * HW + hw;
    ob[0]      = x.x;
    ob[HW]     = x.y;
    ob[2 * HW] = x.z;
}

extern "C" void kernel_launch(void* const* d_in, const int* in_sizes, int n_in,
                              void* d_out, int out_size) {
    const float* vi = (const float*)d_in[0];   // [8,3,512,512]
    const float* ir = (const float*)d_in[1];   // [8,1,512,512]

    dim3 pg((D4 * 8 + 255) / 256, N_LUTS);
    lut_pack_kernel<<<pg, 256>>>((const float*)d_in[2], (const float*)d_in[3],
                                 (const float*)d_in[4], (const float*)d_in[5],
                                 (const float*)d_in[6], (const float*)d_in[7]);

    const int total = 8 * 512 * 512;           // 2,097,152
    net_vif_kernel<<<total / 128, 128>>>(vi, ir, (float*)d_out);
}